// round 12
// baseline (speedup 1.0000x reference)
#include <cuda_runtime.h>
#include <cuda_bf16.h>
#include <cstdint>

// Problem constants (fixed shapes from reference setup_inputs)
#define B_   64
#define C_   2
#define T_   128
#define H_   96
#define NSQ_ 3
#define BLK_ 32          // H/NSQ
#define V_   1024        // BLK*BLK
#define NP_  (B_ * T_)   // 8192 planes
#define NCELL_ (B_ * NSQ_ * NSQ_)  // 576 independent LSTM cells
#define PLANE_ (H_ * H_) // 9216 floats per (b,t) plane

// Scratch: gate pre-activations, layout [t][b][ij] as float4 (i,f,g,o)
__device__ float4 g_xgates[NP_ * NSQ_ * NSQ_];   // 73728 float4 = 1.18 MB

// ---------------------------------------------------------------------------
// Kernel 1: x_gates[t,b,i,j,g] = dot(x_block(b,t,i,j), W_ih[i,j,g,:]) + b_ih + b_hh
//
// 288 threads = 9 warps; warp w owns block (i = w/3, j = w%3).
// Each lane keeps its 128 W_ih values in registers (8 iters x 4 gates x float4)
// and grid-strides over (b,t) planes. x is read straight from global with
// coalesced float4 loads: lane l covers row (it*4 + l/8), cols 4*(l%8)..+3
// of the 32x32 block. Every byte of channel-0 x is read exactly once.
// ---------------------------------------------------------------------------
__global__ __launch_bounds__(288, 1)
void gates_kernel(const float* __restrict__ x,
                  const float* __restrict__ W_ih,
                  const float* __restrict__ b_ih,
                  const float* __restrict__ b_hh)
{
    const int lane = threadIdx.x & 31;
    const int wid  = threadIdx.x >> 5;          // 0..8 -> block (i,j)
    const int i    = wid / 3;
    const int j    = wid % 3;

    const int rsub = lane >> 3;                 // 0..3  row sub-index
    const int csub = (lane & 7) << 2;           // 0,4,..,28  col base

    // ---- Preload this warp's W_ih slice into registers (128 floats/lane) ----
    const float* wb = W_ih + (size_t)wid * 4 * V_;
    float4 wr[8][4];
#pragma unroll
    for (int it = 0; it < 8; ++it) {
        const int v0 = (it * 4 + rsub) * BLK_ + csub;
#pragma unroll
        for (int g = 0; g < 4; ++g)
            wr[it][g] = *reinterpret_cast<const float4*>(wb + g * V_ + v0);
    }

    // ---- Biases (same for all planes) ----
    float bias[4];
#pragma unroll
    for (int g = 0; g < 4; ++g)
        bias[g] = __ldg(b_ih + wid * 4 + g) + __ldg(b_hh + wid * 4 + g);

    // Base offset of this warp's block within a plane
    const int blk_off = (i * BLK_) * H_ + j * BLK_;
    const int lane_off = blk_off + rsub * H_ + csub;   // + it*4*H_ per iter

    // ---- Grid-stride over the 8192 (b,t) planes ----
    for (int p = blockIdx.x; p < NP_; p += gridDim.x) {
        const int b = p >> 7;           // p / T_
        const int t = p & (T_ - 1);     // p % T_
        const float* xp = x + ((size_t)(b * C_) * T_ + t) * PLANE_ + lane_off;

        float a0 = 0.f, a1 = 0.f, a2 = 0.f, a3 = 0.f;
#pragma unroll
        for (int it = 0; it < 8; ++it) {
            const float4 xv = *reinterpret_cast<const float4*>(xp + it * 4 * H_);
            a0 += xv.x * wr[it][0].x + xv.y * wr[it][0].y + xv.z * wr[it][0].z + xv.w * wr[it][0].w;
            a1 += xv.x * wr[it][1].x + xv.y * wr[it][1].y + xv.z * wr[it][1].z + xv.w * wr[it][1].w;
            a2 += xv.x * wr[it][2].x + xv.y * wr[it][2].y + xv.z * wr[it][2].z + xv.w * wr[it][2].w;
            a3 += xv.x * wr[it][3].x + xv.y * wr[it][3].y + xv.z * wr[it][3].z + xv.w * wr[it][3].w;
        }

        // Butterfly reduction over the 32 lanes
#pragma unroll
        for (int off = 16; off > 0; off >>= 1) {
            a0 += __shfl_xor_sync(0xFFFFFFFFu, a0, off);
            a1 += __shfl_xor_sync(0xFFFFFFFFu, a1, off);
            a2 += __shfl_xor_sync(0xFFFFFFFFu, a2, off);
            a3 += __shfl_xor_sync(0xFFFFFFFFu, a3, off);
        }

        if (lane == 0) {
            float4 o;
            o.x = a0 + bias[0];
            o.y = a1 + bias[1];
            o.z = a2 + bias[2];
            o.w = a3 + bias[3];
            g_xgates[((size_t)t * B_ + b) * 9 + wid] = o;
        }
    }
}

// ---------------------------------------------------------------------------
// Kernel 2: sequential LSTM scan, one thread per (b,i,j) cell (576 total).
// Gate loads are coalesced float4 and L2-resident (written by kernel 1);
// next step is prefetched so the dependency chain is math-only.
// ---------------------------------------------------------------------------
__device__ __forceinline__ float fsigmoid(float v) {
    return 1.0f / (1.0f + __expf(-v));
}
__device__ __forceinline__ float ftanh(float v) {
    return 2.0f / (1.0f + __expf(-2.0f * v)) - 1.0f;
}

__global__ __launch_bounds__(64)
void lstm_scan_kernel(const float* __restrict__ W_hh,
                      float* __restrict__ out)
{
    const int tid = blockIdx.x * blockDim.x + threadIdx.x;   // 0..575
    if (tid >= NCELL_) return;
    const int ij = tid % 9;

    const float w0 = __ldg(W_hh + ij * 4 + 0);
    const float w1 = __ldg(W_hh + ij * 4 + 1);
    const float w2 = __ldg(W_hh + ij * 4 + 2);
    const float w3 = __ldg(W_hh + ij * 4 + 3);

    float h = 0.f, c = 0.f;
    float4 nx = g_xgates[tid];                 // prefetch t=0
#pragma unroll 4
    for (int t = 0; t < T_; ++t) {
        const float4 g = nx;
        if (t + 1 < T_) nx = g_xgates[(size_t)(t + 1) * NCELL_ + tid];

        const float iv = fsigmoid(g.x + w0 * h);
        const float fv = fsigmoid(g.y + w1 * h);
        const float gv = ftanh   (g.z + w2 * h);
        const float ov = fsigmoid(g.w + w3 * h);
        c = fv * c + iv * gv;
        h = ov * ftanh(c);
        out[(size_t)t * NCELL_ + tid] = h;
    }
}

// ---------------------------------------------------------------------------
// Launch: inputs in metadata order: x, W_ih, W_hh, b_ih, b_hh
// ---------------------------------------------------------------------------
extern "C" void kernel_launch(void* const* d_in, const int* in_sizes, int n_in,
                              void* d_out, int out_size)
{
    const float* x    = (const float*)d_in[0];
    const float* W_ih = (const float*)d_in[1];
    const float* W_hh = (const float*)d_in[2];
    const float* b_ih = (const float*)d_in[3];
    const float* b_hh = (const float*)d_in[4];
    float* out = (float*)d_out;

    // 296 CTAs (2 waves of 1-CTA/SM) x 288 threads; grid-stride over 8192 planes.
    gates_kernel<<<296, 288>>>(x, W_ih, b_ih, b_hh);

    // 576 cells -> 9 CTAs x 64 threads
    lstm_scan_kernel<<<9, 64>>>(W_hh, out);
}

// round 13
// speedup vs baseline: 1.0002x; 1.0002x over previous
#include <cuda_runtime.h>
#include <cuda_bf16.h>
#include <cstdint>

// Problem constants (fixed shapes from reference setup_inputs)
#define B_   64
#define C_   2
#define T_   128
#define H_   96
#define NSQ_ 3
#define BLK_ 32          // H/NSQ
#define V_   1024        // BLK*BLK
#define NP_  (B_ * T_)   // 8192 planes
#define NCELL_ (B_ * NSQ_ * NSQ_)  // 576 independent LSTM cells
#define PLANE_ (H_ * H_) // 9216 floats per (b,t) plane

// Scratch: gate pre-activations, layout [t][b][ij] as float4 (i,f,g,o)
__device__ float4 g_xgates[NP_ * NSQ_ * NSQ_];   // 73728 float4 = 1.18 MB

// ---------------------------------------------------------------------------
// Kernel 1: x_gates[t,b,i,j,g] = dot(x_block(b,t,i,j), W_ih[i,j,g,:]) + b_ih + b_hh
//
// 288 threads = 9 warps; warp w owns block (i = w/3, j = w%3).
// Each lane keeps its 128 W_ih values in registers (8 iters x 4 gates x float4)
// and grid-strides over (b,t) planes. x is read straight from global with
// coalesced float4 loads: lane l covers row (it*4 + l/8), cols 4*(l%8)..+3
// of the 32x32 block. Every byte of channel-0 x is read exactly once.
// ---------------------------------------------------------------------------
__global__ __launch_bounds__(288, 1)
void gates_kernel(const float* __restrict__ x,
                  const float* __restrict__ W_ih,
                  const float* __restrict__ b_ih,
                  const float* __restrict__ b_hh)
{
    const int lane = threadIdx.x & 31;
    const int wid  = threadIdx.x >> 5;          // 0..8 -> block (i,j)
    const int i    = wid / 3;
    const int j    = wid % 3;

    const int rsub = lane >> 3;                 // 0..3  row sub-index
    const int csub = (lane & 7) << 2;           // 0,4,..,28  col base

    // ---- Preload this warp's W_ih slice into registers (128 floats/lane) ----
    const float* wb = W_ih + (size_t)wid * 4 * V_;
    float4 wr[8][4];
#pragma unroll
    for (int it = 0; it < 8; ++it) {
        const int v0 = (it * 4 + rsub) * BLK_ + csub;
#pragma unroll
        for (int g = 0; g < 4; ++g)
            wr[it][g] = *reinterpret_cast<const float4*>(wb + g * V_ + v0);
    }

    // ---- Biases (same for all planes) ----
    float bias[4];
#pragma unroll
    for (int g = 0; g < 4; ++g)
        bias[g] = __ldg(b_ih + wid * 4 + g) + __ldg(b_hh + wid * 4 + g);

    // Base offset of this warp's block within a plane
    const int blk_off = (i * BLK_) * H_ + j * BLK_;
    const int lane_off = blk_off + rsub * H_ + csub;   // + it*4*H_ per iter

    // ---- Grid-stride over the 8192 (b,t) planes ----
    for (int p = blockIdx.x; p < NP_; p += gridDim.x) {
        const int b = p >> 7;           // p / T_
        const int t = p & (T_ - 1);     // p % T_
        const float* xp = x + ((size_t)(b * C_) * T_ + t) * PLANE_ + lane_off;

        float a0 = 0.f, a1 = 0.f, a2 = 0.f, a3 = 0.f;
#pragma unroll
        for (int it = 0; it < 8; ++it) {
            const float4 xv = *reinterpret_cast<const float4*>(xp + it * 4 * H_);
            a0 += xv.x * wr[it][0].x + xv.y * wr[it][0].y + xv.z * wr[it][0].z + xv.w * wr[it][0].w;
            a1 += xv.x * wr[it][1].x + xv.y * wr[it][1].y + xv.z * wr[it][1].z + xv.w * wr[it][1].w;
            a2 += xv.x * wr[it][2].x + xv.y * wr[it][2].y + xv.z * wr[it][2].z + xv.w * wr[it][2].w;
            a3 += xv.x * wr[it][3].x + xv.y * wr[it][3].y + xv.z * wr[it][3].z + xv.w * wr[it][3].w;
        }

        // Butterfly reduction over the 32 lanes
#pragma unroll
        for (int off = 16; off > 0; off >>= 1) {
            a0 += __shfl_xor_sync(0xFFFFFFFFu, a0, off);
            a1 += __shfl_xor_sync(0xFFFFFFFFu, a1, off);
            a2 += __shfl_xor_sync(0xFFFFFFFFu, a2, off);
            a3 += __shfl_xor_sync(0xFFFFFFFFu, a3, off);
        }

        if (lane == 0) {
            float4 o;
            o.x = a0 + bias[0];
            o.y = a1 + bias[1];
            o.z = a2 + bias[2];
            o.w = a3 + bias[3];
            g_xgates[((size_t)t * B_ + b) * 9 + wid] = o;
        }
    }
}

// ---------------------------------------------------------------------------
// Kernel 2: sequential LSTM scan, one thread per (b,i,j) cell (576 total).
// Gate loads are coalesced float4 and L2-resident (written by kernel 1);
// next step is prefetched so the dependency chain is math-only.
// ---------------------------------------------------------------------------
__device__ __forceinline__ float fsigmoid(float v) {
    return 1.0f / (1.0f + __expf(-v));
}
__device__ __forceinline__ float ftanh(float v) {
    return 2.0f / (1.0f + __expf(-2.0f * v)) - 1.0f;
}

__global__ __launch_bounds__(64)
void lstm_scan_kernel(const float* __restrict__ W_hh,
                      float* __restrict__ out)
{
    const int tid = blockIdx.x * blockDim.x + threadIdx.x;   // 0..575
    if (tid >= NCELL_) return;
    const int ij = tid % 9;

    const float w0 = __ldg(W_hh + ij * 4 + 0);
    const float w1 = __ldg(W_hh + ij * 4 + 1);
    const float w2 = __ldg(W_hh + ij * 4 + 2);
    const float w3 = __ldg(W_hh + ij * 4 + 3);

    float h = 0.f, c = 0.f;
    float4 nx = g_xgates[tid];                 // prefetch t=0
#pragma unroll 4
    for (int t = 0; t < T_; ++t) {
        const float4 g = nx;
        if (t + 1 < T_) nx = g_xgates[(size_t)(t + 1) * NCELL_ + tid];

        const float iv = fsigmoid(g.x + w0 * h);
        const float fv = fsigmoid(g.y + w1 * h);
        const float gv = ftanh   (g.z + w2 * h);
        const float ov = fsigmoid(g.w + w3 * h);
        c = fv * c + iv * gv;
        h = ov * ftanh(c);
        out[(size_t)t * NCELL_ + tid] = h;
    }
}

// ---------------------------------------------------------------------------
// Launch: inputs in metadata order: x, W_ih, W_hh, b_ih, b_hh
// ---------------------------------------------------------------------------
extern "C" void kernel_launch(void* const* d_in, const int* in_sizes, int n_in,
                              void* d_out, int out_size)
{
    const float* x    = (const float*)d_in[0];
    const float* W_ih = (const float*)d_in[1];
    const float* W_hh = (const float*)d_in[2];
    const float* b_ih = (const float*)d_in[3];
    const float* b_hh = (const float*)d_in[4];
    float* out = (float*)d_out;

    // 296 CTAs (2 waves of 1-CTA/SM) x 288 threads; grid-stride over 8192 planes.
    gates_kernel<<<296, 288>>>(x, W_ih, b_ih, b_hh);

    // 576 cells -> 9 CTAs x 64 threads
    lstm_scan_kernel<<<9, 64>>>(W_hh, out);
}

// round 14
// speedup vs baseline: 1.0049x; 1.0047x over previous
#include <cuda_runtime.h>
#include <cuda_bf16.h>
#include <cstdint>

// Problem constants (fixed shapes from reference setup_inputs)
#define B_   64
#define C_   2
#define T_   128
#define H_   96
#define NSQ_ 3
#define BLK_ 32          // H/NSQ
#define V_   1024        // BLK*BLK
#define NP_  (B_ * T_)   // 8192 planes
#define NCELL_ (B_ * NSQ_ * NSQ_)  // 576 independent LSTM cells
#define PLANE_ (H_ * H_) // 9216 floats per (b,t) plane

// Scratch: gate pre-activations, layout [t][b][ij] as float4 (i,f,g,o)
__device__ float4 g_xgates[NP_ * NSQ_ * NSQ_];   // 73728 float4 = 1.18 MB

// ---------------------------------------------------------------------------
// Kernel 1: x_gates[t,b,i,j,g] = dot(x_block(b,t,i,j), W_ih[i,j,g,:]) + b_ih + b_hh
//
// 288 threads = 9 warps; warp w owns block (i = w/3, j = w%3).
// Each lane keeps its 128 W_ih values in registers (8 iters x 4 gates x float4)
// and grid-strides over (b,t) planes. x is read straight from global with
// coalesced float4 loads: lane l covers row (it*4 + l/8), cols 4*(l%8)..+3
// of the 32x32 block. Every byte of channel-0 x is read exactly once.
// ---------------------------------------------------------------------------
__global__ __launch_bounds__(288, 1)
void gates_kernel(const float* __restrict__ x,
                  const float* __restrict__ W_ih,
                  const float* __restrict__ b_ih,
                  const float* __restrict__ b_hh)
{
    const int lane = threadIdx.x & 31;
    const int wid  = threadIdx.x >> 5;          // 0..8 -> block (i,j)
    const int i    = wid / 3;
    const int j    = wid % 3;

    const int rsub = lane >> 3;                 // 0..3  row sub-index
    const int csub = (lane & 7) << 2;           // 0,4,..,28  col base

    // ---- Preload this warp's W_ih slice into registers (128 floats/lane) ----
    const float* wb = W_ih + (size_t)wid * 4 * V_;
    float4 wr[8][4];
#pragma unroll
    for (int it = 0; it < 8; ++it) {
        const int v0 = (it * 4 + rsub) * BLK_ + csub;
#pragma unroll
        for (int g = 0; g < 4; ++g)
            wr[it][g] = *reinterpret_cast<const float4*>(wb + g * V_ + v0);
    }

    // ---- Biases (same for all planes) ----
    float bias[4];
#pragma unroll
    for (int g = 0; g < 4; ++g)
        bias[g] = __ldg(b_ih + wid * 4 + g) + __ldg(b_hh + wid * 4 + g);

    // Base offset of this warp's block within a plane
    const int blk_off = (i * BLK_) * H_ + j * BLK_;
    const int lane_off = blk_off + rsub * H_ + csub;   // + it*4*H_ per iter

    // ---- Grid-stride over the 8192 (b,t) planes ----
    for (int p = blockIdx.x; p < NP_; p += gridDim.x) {
        const int b = p >> 7;           // p / T_
        const int t = p & (T_ - 1);     // p % T_
        const float* xp = x + ((size_t)(b * C_) * T_ + t) * PLANE_ + lane_off;

        float a0 = 0.f, a1 = 0.f, a2 = 0.f, a3 = 0.f;
#pragma unroll
        for (int it = 0; it < 8; ++it) {
            const float4 xv = *reinterpret_cast<const float4*>(xp + it * 4 * H_);
            a0 += xv.x * wr[it][0].x + xv.y * wr[it][0].y + xv.z * wr[it][0].z + xv.w * wr[it][0].w;
            a1 += xv.x * wr[it][1].x + xv.y * wr[it][1].y + xv.z * wr[it][1].z + xv.w * wr[it][1].w;
            a2 += xv.x * wr[it][2].x + xv.y * wr[it][2].y + xv.z * wr[it][2].z + xv.w * wr[it][2].w;
            a3 += xv.x * wr[it][3].x + xv.y * wr[it][3].y + xv.z * wr[it][3].z + xv.w * wr[it][3].w;
        }

        // Butterfly reduction over the 32 lanes
#pragma unroll
        for (int off = 16; off > 0; off >>= 1) {
            a0 += __shfl_xor_sync(0xFFFFFFFFu, a0, off);
            a1 += __shfl_xor_sync(0xFFFFFFFFu, a1, off);
            a2 += __shfl_xor_sync(0xFFFFFFFFu, a2, off);
            a3 += __shfl_xor_sync(0xFFFFFFFFu, a3, off);
        }

        if (lane == 0) {
            float4 o;
            o.x = a0 + bias[0];
            o.y = a1 + bias[1];
            o.z = a2 + bias[2];
            o.w = a3 + bias[3];
            g_xgates[((size_t)t * B_ + b) * 9 + wid] = o;
        }
    }
}

// ---------------------------------------------------------------------------
// Kernel 2: sequential LSTM scan, one thread per (b,i,j) cell (576 total).
// Gate loads are coalesced float4 and L2-resident (written by kernel 1);
// next step is prefetched so the dependency chain is math-only.
// ---------------------------------------------------------------------------
__device__ __forceinline__ float fsigmoid(float v) {
    return 1.0f / (1.0f + __expf(-v));
}
__device__ __forceinline__ float ftanh(float v) {
    return 2.0f / (1.0f + __expf(-2.0f * v)) - 1.0f;
}

__global__ __launch_bounds__(64)
void lstm_scan_kernel(const float* __restrict__ W_hh,
                      float* __restrict__ out)
{
    const int tid = blockIdx.x * blockDim.x + threadIdx.x;   // 0..575
    if (tid >= NCELL_) return;
    const int ij = tid % 9;

    const float w0 = __ldg(W_hh + ij * 4 + 0);
    const float w1 = __ldg(W_hh + ij * 4 + 1);
    const float w2 = __ldg(W_hh + ij * 4 + 2);
    const float w3 = __ldg(W_hh + ij * 4 + 3);

    float h = 0.f, c = 0.f;
    float4 nx = g_xgates[tid];                 // prefetch t=0
#pragma unroll 4
    for (int t = 0; t < T_; ++t) {
        const float4 g = nx;
        if (t + 1 < T_) nx = g_xgates[(size_t)(t + 1) * NCELL_ + tid];

        const float iv = fsigmoid(g.x + w0 * h);
        const float fv = fsigmoid(g.y + w1 * h);
        const float gv = ftanh   (g.z + w2 * h);
        const float ov = fsigmoid(g.w + w3 * h);
        c = fv * c + iv * gv;
        h = ov * ftanh(c);
        out[(size_t)t * NCELL_ + tid] = h;
    }
}

// ---------------------------------------------------------------------------
// Launch: inputs in metadata order: x, W_ih, W_hh, b_ih, b_hh
// ---------------------------------------------------------------------------
extern "C" void kernel_launch(void* const* d_in, const int* in_sizes, int n_in,
                              void* d_out, int out_size)
{
    const float* x    = (const float*)d_in[0];
    const float* W_ih = (const float*)d_in[1];
    const float* W_hh = (const float*)d_in[2];
    const float* b_ih = (const float*)d_in[3];
    const float* b_hh = (const float*)d_in[4];
    float* out = (float*)d_out;

    // 296 CTAs (2 waves of 1-CTA/SM) x 288 threads; grid-stride over 8192 planes.
    gates_kernel<<<296, 288>>>(x, W_ih, b_ih, b_hh);

    // 576 cells -> 9 CTAs x 64 threads
    lstm_scan_kernel<<<9, 64>>>(W_hh, out);
}